// round 2
// baseline (speedup 1.0000x reference)
#include <cuda_runtime.h>
#include <math.h>

#define Hdim 512
#define G4   2048
#define NB   256      // B*U lstm lanes
#define LT   64       // timesteps
#define BB   8
#define UU   32
#define SS   2048
#define EE   128
#define NNODE 33      // U+1

// ---------------- scratch (device globals; no allocations allowed) ----------
__device__ float g_x  [(size_t)LT*NB*Hdim];   // embedded inputs, [t*256+n][h]
__device__ float g_gx [(size_t)LT*NB*G4];     // x @ W_ih + b,  [t*256+n][4H]
__device__ float g_ys [(size_t)LT*NB*Hdim];   // h per step,    [t*256+n][h]
__device__ float g_h  [2][NB*Hdim];           // double-buffered hidden state
__device__ float g_c  [NB*Hdim];              // cell state (in-place)
__device__ float g_nodes[BB*NNODE*Hdim];
__device__ float g_msg  [(size_t)BB*EE*Hdim];
__device__ float g_agg  [BB*NNODE*Hdim];
__device__ float g_new  [BB*NNODE*Hdim];

// ---------------- output offsets (pytree flatten order) ---------------------
#define OFF_ENCH 0
#define OFF_ENCC 4096
#define OFF_MB   8192
#define OFF_LEN1 (8192 + 8388608)            // 8396800
#define OFF_MBU  (OFF_LEN1 + 8)              // 8396808
#define OFF_LEN2 (OFF_MBU + 8388608)         // 16785416
#define OFF_HIER (OFF_LEN2 + 8)              // 16785424

__device__ __forceinline__ float sigmf(float x){ return 1.0f/(1.0f+expf(-x)); }

// ---------------- init: zero h0, c0 ----------------------------------------
__global__ void k_zero(){
  int i = blockIdx.x*blockDim.x + threadIdx.x;
  if (i < NB*Hdim){ g_h[0][i] = 0.0f; g_c[i] = 0.0f; }
}

// ---------------- embedding gather -----------------------------------------
__global__ void k_embed(const int* __restrict__ src, const int* __restrict__ speaker,
                        const float* __restrict__ emb, const float* __restrict__ spkt){
  int row = blockIdx.x;            // t*256 + n
  int t = row >> 8, n = row & 255;
  int b = n >> 5, u = n & 31;
  int s = u*LT + t;
  int w  = src[s*BB + b];          // src (S,B,1)
  int sp = speaker[b*SS + s];      // speaker (B,S)
  const float* er = emb  + (size_t)w  * Hdim;
  const float* sr = spkt + (size_t)sp * Hdim;
  float* xr = g_x + (size_t)row * Hdim;
  for (int h = threadIdx.x; h < Hdim; h += blockDim.x)
    xr[h] = er[h] + sr[h];
}

// ---------------- Gx = x @ W_ih + b ; M=16384 N=2048 K=512 ------------------
__global__ void __launch_bounds__(256) k_gx_gemm(const float* __restrict__ Wih,
                                                 const float* __restrict__ bias){
  const int K = Hdim, N = G4;
  __shared__ float As[16][64];
  __shared__ float Bs[16][64];
  int tid = threadIdx.x;
  int m0 = blockIdx.y*64, n0 = blockIdx.x*64;
  int tr = tid>>4, tc = tid&15;
  int arow = tid>>2,  acol = (tid&3)<<2;
  int brow = tid>>4,  bcol = (tid&15)<<2;
  float acc[4][4] = {};
  for (int k0 = 0; k0 < K; k0 += 16){
    float4 av = *(const float4*)(g_x + (size_t)(m0+arow)*K + k0 + acol);
    As[acol  ][arow] = av.x; As[acol+1][arow] = av.y;
    As[acol+2][arow] = av.z; As[acol+3][arow] = av.w;
    float4 bv = *(const float4*)(Wih + (size_t)(k0+brow)*N + n0 + bcol);
    *(float4*)&Bs[brow][bcol] = bv;
    __syncthreads();
    #pragma unroll
    for (int kk = 0; kk < 16; kk++){
      float4 am = *(float4*)&As[kk][tr<<2];
      float4 bn = *(float4*)&Bs[kk][tc<<2];
      acc[0][0]+=am.x*bn.x; acc[0][1]+=am.x*bn.y; acc[0][2]+=am.x*bn.z; acc[0][3]+=am.x*bn.w;
      acc[1][0]+=am.y*bn.x; acc[1][1]+=am.y*bn.y; acc[1][2]+=am.y*bn.z; acc[1][3]+=am.y*bn.w;
      acc[2][0]+=am.z*bn.x; acc[2][1]+=am.z*bn.y; acc[2][2]+=am.z*bn.z; acc[2][3]+=am.z*bn.w;
      acc[3][0]+=am.w*bn.x; acc[3][1]+=am.w*bn.y; acc[3][2]+=am.w*bn.z; acc[3][3]+=am.w*bn.w;
    }
    __syncthreads();
  }
  #pragma unroll
  for (int i = 0; i < 4; i++){
    int mrow = m0 + (tr<<2) + i;
    #pragma unroll
    for (int j = 0; j < 4; j++){
      int ncol = n0 + (tc<<2) + j;
      g_gx[(size_t)mrow*N + ncol] = acc[i][j] + bias[ncol];
    }
  }
}

// ---------------- fused LSTM step: gates = Gx[t] + h@W_hh; activations ------
// grid (16 j-tiles, 8 m-tiles), 256 threads. tile = 32 rows x 32 j (128 gate cols)
__global__ void __launch_bounds__(256) k_lstm_step(const float* __restrict__ Whh, int t){
  const float* hprev = g_h[t & 1];
  float*       hnext = g_h[(t+1) & 1];
  const float* gx = g_gx + (size_t)t*NB*G4;
  float*       ys = g_ys + (size_t)t*NB*Hdim;
  __shared__ float As[32][33];
  __shared__ float Bs[32][128];
  int tid = threadIdx.x;
  int m0 = blockIdx.y << 5;
  int j0 = blockIdx.x << 5;
  int r  = tid >> 3;          // 0..31 row in tile
  int jl = (tid & 7) << 2;    // 0..28 j-offset
  float acc[4][4] = {};       // [gate][jj]
  for (int k0 = 0; k0 < Hdim; k0 += 32){
    int ac = (tid & 7) << 2;
    float4 av = *(const float4*)(hprev + (size_t)(m0+r)*Hdim + k0 + ac);
    As[r][ac] = av.x; As[r][ac+1] = av.y; As[r][ac+2] = av.z; As[r][ac+3] = av.w;
    int c4 = (tid & 31) << 2;          // 0..124
    int gg = c4 >> 5, jj = c4 & 31;
    int kr0 = (tid >> 5) << 2;         // 0..28
    #pragma unroll
    for (int rr = 0; rr < 4; rr++){
      float4 bv = *(const float4*)(Whh + (size_t)(k0+kr0+rr)*G4 + gg*Hdim + j0 + jj);
      *(float4*)&Bs[kr0+rr][c4] = bv;
    }
    __syncthreads();
    #pragma unroll
    for (int kk = 0; kk < 32; kk++){
      float a = As[r][kk];
      #pragma unroll
      for (int gq = 0; gq < 4; gq++){
        float4 bv = *(float4*)&Bs[kk][(gq<<5) + jl];
        acc[gq][0] += a*bv.x; acc[gq][1] += a*bv.y;
        acc[gq][2] += a*bv.z; acc[gq][3] += a*bv.w;
      }
    }
    __syncthreads();
  }
  int n = m0 + r;
  #pragma unroll
  for (int q = 0; q < 4; q++){
    int j = j0 + jl + q;
    float iv = acc[0][q] + gx[(size_t)n*G4 + j];
    float fv = acc[1][q] + gx[(size_t)n*G4 + Hdim + j];
    float gv = acc[2][q] + gx[(size_t)n*G4 + 2*Hdim + j];
    float ov = acc[3][q] + gx[(size_t)n*G4 + 3*Hdim + j];
    float cv = sigmf(fv)*g_c[n*Hdim + j] + sigmf(iv)*tanhf(gv);
    float hv = sigmf(ov)*tanhf(cv);
    g_c[n*Hdim + j] = cv;
    hnext[n*Hdim + j] = hv;
    ys[n*Hdim + j] = hv;
  }
}

// ---------------- GNN: build nodes (utt_h rows + mean) ----------------------
__global__ void k_nodes(){
  int b = blockIdx.x, h = threadIdx.x;
  const float* last = g_ys + (size_t)(LT-1)*NB*Hdim;   // hT
  float s = 0.0f;
  for (int u = 0; u < UU; u++){
    float v = last[(size_t)(b*UU + u)*Hdim + h];
    g_nodes[(size_t)(b*NNODE + u)*Hdim + h] = v;
    s += v;
  }
  g_nodes[(size_t)(b*NNODE + UU)*Hdim + h] = s * (1.0f/UU);
}

// ---------------- per-edge message: msg = nodes[src] @ W_rel[rel] -----------
__global__ void __launch_bounds__(256) k_msg(const int* __restrict__ edge_src,
                                             const int* __restrict__ rels,
                                             const float* __restrict__ Wrel){
  int be = blockIdx.x;              // b*128 + e
  int b = be >> 7;
  int rel = rels[be];
  int es  = edge_src[be];
  __shared__ float xs[Hdim];
  int tid = threadIdx.x;
  xs[tid]     = g_nodes[(size_t)(b*NNODE + es)*Hdim + tid];
  xs[tid+256] = g_nodes[(size_t)(b*NNODE + es)*Hdim + tid + 256];
  __syncthreads();
  const float* W = Wrel + (size_t)rel*Hdim*Hdim;
  float a0 = 0.0f, a1 = 0.0f;
  for (int k = 0; k < Hdim; k++){
    float xv = xs[k];
    a0 += xv * W[(size_t)k*Hdim + tid];
    a1 += xv * W[(size_t)k*Hdim + tid + 256];
  }
  g_msg[(size_t)be*Hdim + tid]       = a0;
  g_msg[(size_t)be*Hdim + tid + 256] = a1;
}

// ---------------- deterministic segment-sum over edges ----------------------
__global__ void k_agg(const int* __restrict__ edge_dst){
  int bd = blockIdx.x;              // b*33 + d
  int b = bd / NNODE, d = bd % NNODE;
  int h = threadIdx.x;
  float a = 0.0f;
  for (int e = 0; e < EE; e++){
    if (edge_dst[b*EE + e] == d)
      a += g_msg[(size_t)(b*EE + e)*Hdim + h];
  }
  g_agg[(size_t)bd*Hdim + h] = a;
}

// ---------------- GNN output/gate fusion ------------------------------------
__global__ void __launch_bounds__(256) k_gnn(const float* __restrict__ Wself,
                                             const float* __restrict__ bg,
                                             const float* __restrict__ Wg1,
                                             const float* __restrict__ Wg2){
  int bd = blockIdx.x;
  __shared__ float nd[Hdim], ag[Hdim];
  int tid = threadIdx.x;
  nd[tid]     = g_nodes[(size_t)bd*Hdim + tid];
  nd[tid+256] = g_nodes[(size_t)bd*Hdim + tid + 256];
  ag[tid]     = g_agg[(size_t)bd*Hdim + tid];
  ag[tid+256] = g_agg[(size_t)bd*Hdim + tid + 256];
  __syncthreads();
  for (int jo = 0; jo < 2; jo++){
    int j = tid + jo*256;
    float s1 = 0.0f, s2 = 0.0f, s3 = 0.0f;
    for (int k = 0; k < Hdim; k++){
      float nv = nd[k], av = ag[k];
      s1 += nv * Wself[(size_t)k*Hdim + j];
      s2 += nv * Wg1  [(size_t)k*Hdim + j];
      s3 += av * Wg2  [(size_t)k*Hdim + j];
    }
    float outv = s1 + ag[j] + bg[j];
    outv = outv > 0.0f ? outv : 0.0f;
    float gate = sigmf(s2 + s3);
    g_new[(size_t)bd*Hdim + j] = gate*outv + (1.0f - gate)*nd[j];
  }
}

// ---------------- output writers --------------------------------------------
__global__ void k_out_small(float* __restrict__ dout, const int* __restrict__ lengths){
  int i = blockIdx.x*blockDim.x + threadIdx.x;   // 0..16383
  if (i < 4096){
    int b = i >> 9, h = i & 511;
    float v = g_new[(size_t)(b*NNODE + UU)*Hdim + h];   // global_reps
    dout[OFF_ENCH + i] = v;
    dout[OFF_ENCC + i] = v;
  }
  if (i < 8){
    float lv = (float)lengths[i];
    dout[OFF_LEN1 + i] = lv;
    dout[OFF_LEN2 + i] = lv;
  }
  dout[OFF_HIER + i] = (float)LT;   // hier_matrix == L everywhere
}

// fused memory_bank + mbu writer: one thread per (s,b,h) coordinate, 2 stores
__global__ void k_big_out(float* __restrict__ dout){
  size_t i = (size_t)blockIdx.x*blockDim.x + threadIdx.x;
  if (i >= (size_t)SS*BB*Hdim) return;
  int h = (int)(i & 511);
  int b = (int)((i >> 9) & 7);
  int s = (int)(i >> 12);
  int t = s & 63, u = s >> 6;
  dout[OFF_MB  + i] = g_ys[((size_t)t*NB + b*UU + u)*Hdim + h];
  dout[OFF_MBU + i] = g_new[(size_t)(b*NNODE + u)*Hdim + h];
}

// ---------------- driver -----------------------------------------------------
extern "C" void kernel_launch(void* const* d_in, const int* in_sizes, int n_in,
                              void* d_out, int out_size){
  const int*   src      = (const int*)  d_in[0];
  // d_in[1] = seg (unused by reference)
  const int*   speaker  = (const int*)  d_in[2];
  const int*   lengths  = (const int*)  d_in[3];
  const int*   edge_src = (const int*)  d_in[4];
  const int*   edge_dst = (const int*)  d_in[5];
  const int*   rels     = (const int*)  d_in[6];
  const float* emb      = (const float*)d_in[7];
  const float* spkt     = (const float*)d_in[8];
  const float* Wih      = (const float*)d_in[9];
  const float* Whh      = (const float*)d_in[10];
  const float* bl       = (const float*)d_in[11];
  const float* Wrel     = (const float*)d_in[12];
  const float* Wself    = (const float*)d_in[13];
  const float* bg       = (const float*)d_in[14];
  const float* Wg1      = (const float*)d_in[15];
  const float* Wg2      = (const float*)d_in[16];
  float* dout = (float*)d_out;

  k_zero<<<512, 256>>>();
  k_embed<<<LT*NB, 256>>>(src, speaker, emb, spkt);
  k_gx_gemm<<<dim3(G4/64, (LT*NB)/64), 256>>>(Wih, bl);
  for (int t = 0; t < LT; t++)
    k_lstm_step<<<dim3(16, 8), 256>>>(Whh, t);
  k_nodes<<<BB, 512>>>();
  k_msg<<<BB*EE, 256>>>(edge_src, rels, Wrel);
  k_agg<<<BB*NNODE, 512>>>(edge_dst);
  k_gnn<<<BB*NNODE, 256>>>(Wself, bg, Wg1, Wg2);
  k_out_small<<<64, 256>>>(dout, lengths);
  k_big_out<<<32768, 256>>>(dout);
}